// round 14
// baseline (speedup 1.0000x reference)
#include <cuda_runtime.h>
#include <cuda_fp16.h>
#include <cstdint>

// ---------------------------------------------------------------------------
// SwinV2 block: B=32, H=W=64, C=256, NH=8, HD=32, WS=8, SS=4
// Round 14: BM128xBN256 GEMM (warp tile 64x64, 8:32 LDSM:MMA), 3-stage
// cp.async; HMMA-tensorized attention; fp16 intermediates.
// ---------------------------------------------------------------------------

static constexpr int SSc   = 4;
static constexpr int NTOK  = 64;
static constexpr int NHc   = 8;
static constexpr int Cc    = 256;
static constexpr int MROWS = 131072;
static constexpr int HIDc  = 1024;

__device__ __half g_qkvh[(size_t)MROWS * 768];
__device__ __half g_attn[(size_t)MROWS * Cc];
__device__ float  g_y   [(size_t)MROWS * Cc];
__device__ float  g_x1  [(size_t)MROWS * Cc];
__device__ __half g_x1h [(size_t)MROWS * Cc];
__device__ __half g_h   [(size_t)MROWS * HIDc];
__device__ float  g_h2  [(size_t)MROWS * Cc];
__device__ __half g_xh  [(size_t)MROWS * Cc];
__device__ float  g_rpb [NHc * NTOK * NTOK];
__device__ float  g_qkvbias[768];
__device__ float  g_hscale[NHc];
__device__ int    g_rowmap[MROWS];
__device__ __half g_wqkv_h[768 * 256];
__device__ __half g_wproj_h[256 * 256];
__device__ __half g_wfc1_h[1024 * 256];
__device__ __half g_wfc2_h[256 * 1024];

__device__ __forceinline__ float gelu_f(float x) {
    float x3 = x * x * x;
    return 0.5f * x * (1.f + tanhf(0.7978845608028654f * (x + 0.044715f * x3)));
}
__device__ __forceinline__ uint32_t smem_u32(const void* p) {
    uint32_t a;
    asm("{ .reg .u64 t; cvta.to.shared.u64 t, %1; cvt.u32.u64 %0, t; }" : "=r"(a) : "l"(p));
    return a;
}
__device__ __forceinline__ void mma_f16(float* c, const unsigned* a, const unsigned* b) {
    asm volatile(
        "mma.sync.aligned.m16n8k16.row.col.f32.f16.f16.f32 "
        "{%0,%1,%2,%3}, {%4,%5,%6,%7}, {%8,%9}, {%0,%1,%2,%3};"
        : "+f"(c[0]), "+f"(c[1]), "+f"(c[2]), "+f"(c[3])
        : "r"(a[0]), "r"(a[1]), "r"(a[2]), "r"(a[3]), "r"(b[0]), "r"(b[1]));
}
__device__ __forceinline__ void ldsm4(unsigned* r, uint32_t addr) {
    asm volatile("ldmatrix.sync.aligned.m8n8.x4.shared.b16 {%0,%1,%2,%3}, [%4];"
        : "=r"(r[0]), "=r"(r[1]), "=r"(r[2]), "=r"(r[3]) : "r"(addr));
}
__device__ __forceinline__ void ldsm4t(unsigned* r, uint32_t addr) {
    asm volatile("ldmatrix.sync.aligned.m8n8.x4.trans.shared.b16 {%0,%1,%2,%3}, [%4];"
        : "=r"(r[0]), "=r"(r[1]), "=r"(r[2]), "=r"(r[3]) : "r"(addr));
}
__device__ __forceinline__ void cp16(uint32_t dst, const void* src) {
    asm volatile("cp.async.cg.shared.global [%0], [%1], 16;" :: "r"(dst), "l"(src));
}
__device__ __forceinline__ unsigned pack_h2(float a, float b) {
    __half2 h = __floats2half2_rn(a, b);
    return *(unsigned*)&h;
}

// ---------------------------------------------------------------------------
__global__ void prep_kernel(const float* __restrict__ logit_scale,
                            const float* __restrict__ cpb_w1,
                            const float* __restrict__ cpb_b1,
                            const float* __restrict__ cpb_w2,
                            const float* __restrict__ q_bias,
                            const float* __restrict__ v_bias) {
    __shared__ float table[225][NHc];
    int t = threadIdx.x;
    for (int i = t; i < 768; i += 256) {
        float v = 0.f;
        if (i < 256)       v = q_bias[i];
        else if (i >= 512) v = v_bias[i - 512];
        g_qkvbias[i] = v;
    }
    if (t < NHc) {
        float ls = logit_scale[t];
        g_hscale[t] = expf(fminf(ls, 4.605170185988092f));
    }
    if (t < 225) {
        int a = t / 15, b = t % 15;
        float f0 = (float)(a - 7) * (8.f / 7.f);
        float f1 = (float)(b - 7) * (8.f / 7.f);
        f0 = copysignf(log2f(fabsf(f0) + 1.f) * (1.f / 3.f), f0);
        f1 = copysignf(log2f(fabsf(f1) + 1.f) * (1.f / 3.f), f1);
        float acc[NHc];
        #pragma unroll
        for (int h = 0; h < NHc; h++) acc[h] = 0.f;
        for (int j = 0; j < 512; j++) {
            float hid = f0 * cpb_w1[j] + f1 * cpb_w1[512 + j] + cpb_b1[j];
            hid = fmaxf(hid, 0.f);
            #pragma unroll
            for (int h = 0; h < NHc; h++) acc[h] += hid * cpb_w2[j * NHc + h];
        }
        #pragma unroll
        for (int h = 0; h < NHc; h++) table[t][h] = acc[h];
    }
    __syncthreads();
    for (int idx = t; idx < NHc * NTOK * NTOK; idx += 256) {
        int h = idx >> 12, rem = idx & 4095, i = rem >> 6, j = rem & 63;
        int iy = i >> 3, ix = i & 7, jy = j >> 3, jx = j & 7;
        int ti = (iy - jy + 7) * 15 + (ix - jx + 7);
        float v = table[ti][h];
        g_rpb[idx] = 16.f / (1.f + expf(-v));
    }
}

__global__ void rowmap_kernel() {
    int r = blockIdx.x * 256 + threadIdx.x;
    if (r >= MROWS) return;
    int b = r >> 12;
    int rem = r & 4095;
    int w = rem >> 6, n = rem & 63;
    int wy = w >> 3, wx = w & 7, ty = n >> 3, tx = n & 7;
    int hs = (wy * 8 + ty + SSc) & 63;
    int ws = (wx * 8 + tx + SSc) & 63;
    g_rowmap[r] = (b << 12) + (hs << 6) + ws;
}

__global__ void xgather_kernel(const float* __restrict__ x) {
    int idx = blockIdx.x * 256 + threadIdx.x;
    int base = idx << 3;
    int row = base >> 8, col = base & 255;
    int b = row >> 12, rem = row & 4095;
    int w = rem >> 6, n = rem & 63;
    int wy = w >> 3, wx = w & 7, ty = n >> 3, tx = n & 7;
    int hs = (wy * 8 + ty + SSc) & 63;
    int ws = (wx * 8 + tx + SSc) & 63;
    int src = (b << 12) + (hs << 6) + ws;
    const float* p = x + (size_t)src * 256 + col;
    float4 f0 = *(const float4*)p;
    float4 f1 = *(const float4*)(p + 4);
    uint4 u;
    u.x = pack_h2(f0.x, f0.y); u.y = pack_h2(f0.z, f0.w);
    u.z = pack_h2(f1.x, f1.y); u.w = pack_h2(f1.z, f1.w);
    *(uint4*)(g_xh + (size_t)row * 256 + col) = u;
}

__global__ void wtrans_kernel(const float* __restrict__ W, __half* __restrict__ Wt,
                              int K, int N) {
    int idx = blockIdx.x * 256 + threadIdx.x;
    if (idx >= K * N) return;
    int n = idx / K, k = idx - n * K;
    Wt[idx] = __float2half_rn(W[(size_t)k * N + n]);
}

// ---------------------------------------------------------------------------
// fp16 GEMM, BM=128, BN=256, BK=32, 3-stage cp.async pipeline.
// 8 warps (2m x 4n), warp tile 64x64. A fp16 [M,K]; B fp16 [N,K] K-major.
// smem stride 40 halfs; ldmatrix.x4; per-ks 8 LDSM : 32 MMA.
// ---------------------------------------------------------------------------
static constexpr int G_STRIDE  = 40;                   // halfs per row
static constexpr int A_STAGEB  = 128 * G_STRIDE * 2;   // 10240 B
static constexpr int B_STAGEB  = 256 * G_STRIDE * 2;   // 20480 B
static constexpr int SMEM_GEMM = 3 * (A_STAGEB + B_STAGEB);  // 92160

template<bool GELU, bool SCATTER_C, bool OUT_HALF>
__global__ __launch_bounds__(256, 1)
void gemm_f16(const __half* __restrict__ A, const __half* __restrict__ Bt,
              const float* __restrict__ bias, void* __restrict__ Cm,
              int N, int K, const int* __restrict__ rowmap) {
    extern __shared__ __align__(16) unsigned char gsm[];
    __half* As = (__half*)gsm;                          // 3 stages
    __half* Bs = (__half*)(gsm + 3 * A_STAGEB);         // 3 stages

    const int t = threadIdx.x;
    const int lane = t & 31, wid = t >> 5;
    const int wm = (wid >> 2) << 6;   // 0 or 64
    const int wn = (wid & 3) << 6;    // 0,64,128,192
    const int m0 = blockIdx.y * 128, n0 = blockIdx.x * 256;

    // A loader: row t>>1, 16 halfs at (t&1)*16 (2 cp16)
    const int am = t >> 1;
    const int ak = (t & 1) << 4;
    const __half* ap = A + (size_t)(m0 + am) * K + ak;
    const uint32_t a_dst = smem_u32(As + am * G_STRIDE + ak);
    // B loader: row t, 32 halfs (4 cp16)
    const __half* bp = Bt + (size_t)(n0 + t) * K;
    const uint32_t b_dst = smem_u32(Bs + t * G_STRIDE);

    const int quad = lane >> 3, lr = lane & 7;
    const uint32_t a_addr0 = smem_u32(As + (wm + ((quad & 1) << 3) + lr) * G_STRIDE
                                         + ((quad >> 1) << 3));
    const uint32_t b_addr0 = smem_u32(Bs + (wn + ((quad >> 1) << 3) + lr) * G_STRIDE
                                         + ((quad & 1) << 3));
    const uint32_t MTB = 16 * G_STRIDE * 2;             // 16 rows in bytes

    float acc[4][8][4];
    #pragma unroll
    for (int i = 0; i < 4; i++)
        #pragma unroll
        for (int j = 0; j < 8; j++)
            #pragma unroll
            for (int r = 0; r < 4; r++) acc[i][j][r] = 0.f;

    const int KT = K >> 5;   // BK=32

    // prologue: stages 0,1
    #pragma unroll
    for (int s = 0; s < 2; s++) {
        const __half* asrc = ap + s * 32;
        const __half* bsrc = bp + s * 32;
        cp16(a_dst + s * A_STAGEB, asrc);
        cp16(a_dst + s * A_STAGEB + 16, asrc + 8);
        cp16(b_dst + s * B_STAGEB, bsrc);
        cp16(b_dst + s * B_STAGEB + 16, bsrc + 8);
        cp16(b_dst + s * B_STAGEB + 32, bsrc + 16);
        cp16(b_dst + s * B_STAGEB + 48, bsrc + 24);
        asm volatile("cp.async.commit_group;" ::: "memory");
    }

    int cur = 0;
    for (int kt = 0; kt < KT; kt++) {
        if (kt == KT - 1) asm volatile("cp.async.wait_group 0;" ::: "memory");
        else              asm volatile("cp.async.wait_group 1;" ::: "memory");
        __syncthreads();

        if (kt + 2 < KT) {
            int st = kt + 2;
            int sb = st - (st / 3) * 3;
            const __half* asrc = ap + st * 32;
            const __half* bsrc = bp + st * 32;
            cp16(a_dst + sb * A_STAGEB, asrc);
            cp16(a_dst + sb * A_STAGEB + 16, asrc + 8);
            cp16(b_dst + sb * B_STAGEB, bsrc);
            cp16(b_dst + sb * B_STAGEB + 16, bsrc + 8);
            cp16(b_dst + sb * B_STAGEB + 32, bsrc + 16);
            cp16(b_dst + sb * B_STAGEB + 48, bsrc + 24);
            asm volatile("cp.async.commit_group;" ::: "memory");
        }

        #pragma unroll
        for (int ks = 0; ks < 2; ks++) {
            const uint32_t ab = a_addr0 + cur * A_STAGEB + ks * 32;
            const uint32_t bb = b_addr0 + cur * B_STAGEB + ks * 32;
            unsigned af[4][4], bf[8][2];
            #pragma unroll
            for (int mt = 0; mt < 4; mt++) ldsm4(af[mt], ab + mt * MTB);
            #pragma unroll
            for (int j = 0; j < 4; j++) {
                unsigned tmp[4];
                ldsm4(tmp, bb + j * MTB);
                bf[2 * j][0] = tmp[0]; bf[2 * j][1] = tmp[1];
                bf[2 * j + 1][0] = tmp[2]; bf[2 * j + 1][1] = tmp[3];
            }
            #pragma unroll
            for (int mt = 0; mt < 4; mt++)
                #pragma unroll
                for (int nt = 0; nt < 8; nt++)
                    mma_f16(acc[mt][nt], af[mt], bf[nt]);
        }

        if (++cur == 3) cur = 0;
    }

    // epilogue
    #pragma unroll
    for (int mt = 0; mt < 4; mt++) {
        int rr = m0 + wm + (mt << 4) + (lane >> 2);
        int r2 = rr + 8;
        int o1 = SCATTER_C ? rowmap[rr] : rr;
        int o2 = SCATTER_C ? rowmap[r2] : r2;
        #pragma unroll
        for (int nt = 0; nt < 8; nt++) {
            int c = n0 + wn + (nt << 3) + ((lane & 3) << 1);
            float b0 = bias[c], b1 = bias[c + 1];
            float2 v0, v1;
            v0.x = acc[mt][nt][0] + b0;
            v0.y = acc[mt][nt][1] + b1;
            v1.x = acc[mt][nt][2] + b0;
            v1.y = acc[mt][nt][3] + b1;
            if (GELU) {
                v0.x = gelu_f(v0.x); v0.y = gelu_f(v0.y);
                v1.x = gelu_f(v1.x); v1.y = gelu_f(v1.y);
            }
            if (OUT_HALF) {
                __half* C = (__half*)Cm;
                *(__half2*)(C + (size_t)o1 * N + c) = __floats2half2_rn(v0.x, v0.y);
                *(__half2*)(C + (size_t)o2 * N + c) = __floats2half2_rn(v1.x, v1.y);
            } else {
                float* C = (float*)Cm;
                *(float2*)(C + (size_t)o1 * N + c) = v0;
                *(float2*)(C + (size_t)o2 * N + c) = v1;
            }
        }
    }
}

// ---------------------------------------------------------------------------
// Tensorized windowed cosine attention (unchanged from round 12).
// ---------------------------------------------------------------------------
static constexpr int BLOB_STRIDE = 776;
static constexpr int SMEM_ATTN = 64 * BLOB_STRIDE * 2 + 2 * 8 * 64 * 4 + 64 * 4;

__global__ __launch_bounds__(256)
void attn_kernel(const __half* __restrict__ qkv, __half* __restrict__ out) {
    extern __shared__ __align__(16) unsigned char dynsm[];
    __half* blob   = (__half*)dynsm;
    float*  invq_s = (float*)(dynsm + 64 * BLOB_STRIDE * 2);
    float*  invk_s = invq_s + 8 * 64;
    int*    lab    = (int*)(invk_s + 8 * 64);

    const int t = threadIdx.x, lane = t & 31, h = t >> 5;
    const int win = blockIdx.x;
    const __half* src = qkv + (size_t)win * 64 * 768;

    #pragma unroll
    for (int c = 0; c < 24; c++) {
        int chunk = c * 256 + t;
        int row = chunk / 96, off = (chunk - row * 96) << 3;
        cp16(smem_u32(blob + row * BLOB_STRIDE + off), src + row * 768 + off);
    }
    asm volatile("cp.async.commit_group;" ::: "memory");
    if (t < 64) {
        int w = win & 63;
        int wy = w >> 3, wx = w & 7, ty_ = t >> 3, tx_ = t & 7;
        int gh = wy * 8 + ty_, gw = wx * 8 + tx_;
        int rh = gh < 56 ? 0 : (gh < 60 ? 1 : 2);
        int rw = gw < 56 ? 0 : (gw < 60 ? 1 : 2);
        lab[t] = rh * 3 + rw;
    }
    asm volatile("cp.async.wait_group 0;" ::: "memory");
    __syncthreads();

    #pragma unroll
    for (int tk = lane; tk < 64; tk += 32) {
        const __half2* qp = (const __half2*)(blob + tk * BLOB_STRIDE + h * 32);
        const __half2* kp = (const __half2*)(blob + tk * BLOB_STRIDE + 256 + h * 32);
        float sq = 0.f, sk = 0.f;
        #pragma unroll
        for (int i = 0; i < 16; i++) {
            float2 f = __half22float2(qp[i]);
            sq += f.x * f.x + f.y * f.y;
            float2 g = __half22float2(kp[i]);
            sk += g.x * g.x + g.y * g.y;
        }
        invq_s[h * 64 + tk] = rsqrtf(fmaxf(sq, 1e-12f));
        invk_s[h * 64 + tk] = rsqrtf(fmaxf(sk, 1e-12f));
    }
    __syncwarp();

    const int quad = lane >> 3, lr = lane & 7;

    unsigned aS[4][2][4];
    #pragma unroll
    for (int mt = 0; mt < 4; mt++)
        #pragma unroll
        for (int kt = 0; kt < 2; kt++) {
            int row = mt * 16 + ((quad & 1) << 3) + lr;
            int col = h * 32 + kt * 16 + ((quad >> 1) << 3);
            ldsm4(aS[mt][kt], smem_u32(blob + row * BLOB_STRIDE + col));
        }

    float acc[4][8][4];
    #pragma unroll
    for (int mt = 0; mt < 4; mt++)
        #pragma unroll
        for (int nt = 0; nt < 8; nt++)
            #pragma unroll
            for (int r = 0; r < 4; r++) acc[mt][nt][r] = 0.f;
    #pragma unroll
    for (int np = 0; np < 4; np++)
        #pragma unroll
        for (int kt = 0; kt < 2; kt++) {
            int row = np * 16 + ((quad >> 1) << 3) + lr;
            int col = 256 + h * 32 + kt * 16 + ((quad & 1) << 3);
            unsigned bt[4];
            ldsm4(bt, smem_u32(blob + row * BLOB_STRIDE + col));
            #pragma unroll
            for (int mt = 0; mt < 4; mt++) {
                mma_f16(acc[mt][2 * np],     aS[mt][kt], bt);
                mma_f16(acc[mt][2 * np + 1], aS[mt][kt], bt + 2);
            }
        }

    const float sc = g_hscale[h];
    const float* rp = g_rpb + h * 4096;
    float ik0[8], ik1[8];
    int   cl0[8], cl1[8];
    #pragma unroll
    for (int nt = 0; nt < 8; nt++) {
        int c0 = nt * 8 + ((lane & 3) << 1);
        ik0[nt] = invk_s[h * 64 + c0];
        ik1[nt] = invk_s[h * 64 + c0 + 1];
        cl0[nt] = lab[c0];
        cl1[nt] = lab[c0 + 1];
    }
    #pragma unroll
    for (int mt = 0; mt < 4; mt++) {
        int r0 = mt * 16 + (lane >> 2), r1 = r0 + 8;
        float f0 = sc * invq_s[h * 64 + r0];
        float f1 = sc * invq_s[h * 64 + r1];
        int l0 = lab[r0], l1 = lab[r1];
        #pragma unroll
        for (int nt = 0; nt < 8; nt++) {
            int c0 = nt * 8 + ((lane & 3) << 1);
            float rp00 = __ldg(rp + r0 * 64 + c0), rp01 = __ldg(rp + r0 * 64 + c0 + 1);
            float rp10 = __ldg(rp + r1 * 64 + c0), rp11 = __ldg(rp + r1 * 64 + c0 + 1);
            acc[mt][nt][0] = acc[mt][nt][0] * f0 * ik0[nt] + rp00 + (l0 == cl0[nt] ? 0.f : -100.f);
            acc[mt][nt][1] = acc[mt][nt][1] * f0 * ik1[nt] + rp01 + (l0 == cl1[nt] ? 0.f : -100.f);
            acc[mt][nt][2] = acc[mt][nt][2] * f1 * ik0[nt] + rp10 + (l1 == cl0[nt] ? 0.f : -100.f);
            acc[mt][nt][3] = acc[mt][nt][3] * f1 * ik1[nt] + rp11 + (l1 == cl1[nt] ? 0.f : -100.f);
        }
        float m0 = -1e30f, m1 = -1e30f;
        #pragma unroll
        for (int nt = 0; nt < 8; nt++) {
            m0 = fmaxf(m0, fmaxf(acc[mt][nt][0], acc[mt][nt][1]));
            m1 = fmaxf(m1, fmaxf(acc[mt][nt][2], acc[mt][nt][3]));
        }
        m0 = fmaxf(m0, __shfl_xor_sync(0xffffffffu, m0, 1));
        m0 = fmaxf(m0, __shfl_xor_sync(0xffffffffu, m0, 2));
        m1 = fmaxf(m1, __shfl_xor_sync(0xffffffffu, m1, 1));
        m1 = fmaxf(m1, __shfl_xor_sync(0xffffffffu, m1, 2));
        float s0 = 0.f, s1 = 0.f;
        #pragma unroll
        for (int nt = 0; nt < 8; nt++) {
            acc[mt][nt][0] = __expf(acc[mt][nt][0] - m0); s0 += acc[mt][nt][0];
            acc[mt][nt][1] = __expf(acc[mt][nt][1] - m0); s0 += acc[mt][nt][1];
            acc[mt][nt][2] = __expf(acc[mt][nt][2] - m1); s1 += acc[mt][nt][2];
            acc[mt][nt][3] = __expf(acc[mt][nt][3] - m1); s1 += acc[mt][nt][3];
        }
        s0 += __shfl_xor_sync(0xffffffffu, s0, 1);
        s0 += __shfl_xor_sync(0xffffffffu, s0, 2);
        s1 += __shfl_xor_sync(0xffffffffu, s1, 1);
        s1 += __shfl_xor_sync(0xffffffffu, s1, 2);
        float i0 = 1.f / s0, i1 = 1.f / s1;
        #pragma unroll
        for (int nt = 0; nt < 8; nt++) {
            acc[mt][nt][0] *= i0; acc[mt][nt][1] *= i0;
            acc[mt][nt][2] *= i1; acc[mt][nt][3] *= i1;
        }
    }

    unsigned pf[4][4][4];
    #pragma unroll
    for (int mt = 0; mt < 4; mt++)
        #pragma unroll
        for (int kt = 0; kt < 4; kt++) {
            pf[mt][kt][0] = pack_h2(acc[mt][2 * kt][0],     acc[mt][2 * kt][1]);
            pf[mt][kt][1] = pack_h2(acc[mt][2 * kt][2],     acc[mt][2 * kt][3]);
            pf[mt][kt][2] = pack_h2(acc[mt][2 * kt + 1][0], acc[mt][2 * kt + 1][1]);
            pf[mt][kt][3] = pack_h2(acc[mt][2 * kt + 1][2], acc[mt][2 * kt + 1][3]);
        }

    float O[4][4][4];
    #pragma unroll
    for (int mt = 0; mt < 4; mt++)
        #pragma unroll
        for (int nt = 0; nt < 4; nt++)
            #pragma unroll
            for (int r = 0; r < 4; r++) O[mt][nt][r] = 0.f;
    #pragma unroll
    for (int kt = 0; kt < 4; kt++)
        #pragma unroll
        for (int np = 0; np < 2; np++) {
            int row = kt * 16 + ((quad & 1) << 3) + lr;
            int col = 512 + h * 32 + np * 16 + ((quad >> 1) << 3);
            unsigned bt[4];
            ldsm4t(bt, smem_u32(blob + row * BLOB_STRIDE + col));
            #pragma unroll
            for (int mt = 0; mt < 4; mt++) {
                mma_f16(O[mt][2 * np],     pf[mt][kt], bt);
                mma_f16(O[mt][2 * np + 1], pf[mt][kt], bt + 2);
            }
        }

    #pragma unroll
    for (int mt = 0; mt < 4; mt++) {
        int r0 = mt * 16 + (lane >> 2);
        #pragma unroll
        for (int nt = 0; nt < 4; nt++) {
            int c0 = nt * 8 + ((lane & 3) << 1);
            __half* op = out + (size_t)(win * 64 + r0) * 256 + h * 32 + c0;
            *(__half2*)op = __floats2half2_rn(O[mt][nt][0], O[mt][nt][1]);
            *(__half2*)(op + 8 * 256) = __floats2half2_rn(O[mt][nt][2], O[mt][nt][3]);
        }
    }
}

// ---------------------------------------------------------------------------
template<bool WRITE_H>
__global__ __launch_bounds__(256)
void ln_add_kernel(const float* __restrict__ resid, const float* __restrict__ y,
                   const float* __restrict__ sc, const float* __restrict__ bi,
                   float* __restrict__ out, __half* __restrict__ outh) {
    int warp = (blockIdx.x * 256 + threadIdx.x) >> 5;
    int lane = threadIdx.x & 31;
    if (warp >= MROWS) return;
    const float* yr = y + (size_t)warp * 256;
    float v[8];
    #pragma unroll
    for (int i = 0; i < 8; i++) v[i] = yr[lane * 8 + i];
    float s = 0.f;
    #pragma unroll
    for (int i = 0; i < 8; i++) s += v[i];
    #pragma unroll
    for (int o = 16; o > 0; o >>= 1) s += __shfl_xor_sync(0xffffffffu, s, o);
    float mean = s * (1.f / 256.f);
    float sq = 0.f;
    #pragma unroll
    for (int i = 0; i < 8; i++) { float d = v[i] - mean; sq += d * d; }
    #pragma unroll
    for (int o = 16; o > 0; o >>= 1) sq += __shfl_xor_sync(0xffffffffu, sq, o);
    float rstd = rsqrtf(sq * (1.f / 256.f) + 1e-6f);
    const float* rr = resid + (size_t)warp * 256;
    float* op = out + (size_t)warp * 256;
    float ov[8];
    #pragma unroll
    for (int i = 0; i < 8; i++) {
        int c = lane * 8 + i;
        ov[i] = rr[c] + (v[i] - mean) * rstd * sc[c] + bi[c];
        op[c] = ov[i];
    }
    if (WRITE_H) {
        uint4 u;
        u.x = pack_h2(ov[0], ov[1]); u.y = pack_h2(ov[2], ov[3]);
        u.z = pack_h2(ov[4], ov[5]); u.w = pack_h2(ov[6], ov[7]);
        *(uint4*)(outh + (size_t)warp * 256 + lane * 8) = u;
    }
}

// ---------------------------------------------------------------------------
extern "C" void kernel_launch(void* const* d_in, const int* in_sizes, int n_in,
                              void* d_out, int out_size) {
    const float* x       = (const float*)d_in[0];
    const float* qkv_w   = (const float*)d_in[1];
    const float* q_bias  = (const float*)d_in[2];
    const float* v_bias  = (const float*)d_in[3];
    const float* lscale  = (const float*)d_in[4];
    const float* cpb_w1  = (const float*)d_in[5];
    const float* cpb_b1  = (const float*)d_in[6];
    const float* cpb_w2  = (const float*)d_in[7];
    const float* proj_w  = (const float*)d_in[8];
    const float* proj_b  = (const float*)d_in[9];
    const float* n1s     = (const float*)d_in[10];
    const float* n1b     = (const float*)d_in[11];
    const float* n2s     = (const float*)d_in[12];
    const float* n2b     = (const float*)d_in[13];
    const float* fc1_w   = (const float*)d_in[14];
    const float* fc1_b   = (const float*)d_in[15];
    const float* fc2_w   = (const float*)d_in[16];
    const float* fc2_b   = (const float*)d_in[17];
    float* out = (float*)d_out;

    void *p_qkvh, *p_attn, *p_y, *p_x1, *p_x1h, *p_h, *p_h2, *p_xh, *p_qb, *p_rm;
    void *p_wqkv, *p_wproj, *p_wfc1, *p_wfc2;
    cudaGetSymbolAddress(&p_qkvh, g_qkvh);
    cudaGetSymbolAddress(&p_attn, g_attn);
    cudaGetSymbolAddress(&p_y,    g_y);
    cudaGetSymbolAddress(&p_x1,   g_x1);
    cudaGetSymbolAddress(&p_x1h,  g_x1h);
    cudaGetSymbolAddress(&p_h,    g_h);
    cudaGetSymbolAddress(&p_h2,   g_h2);
    cudaGetSymbolAddress(&p_xh,   g_xh);
    cudaGetSymbolAddress(&p_qb,   g_qkvbias);
    cudaGetSymbolAddress(&p_rm,   g_rowmap);
    cudaGetSymbolAddress(&p_wqkv,  g_wqkv_h);
    cudaGetSymbolAddress(&p_wproj, g_wproj_h);
    cudaGetSymbolAddress(&p_wfc1,  g_wfc1_h);
    cudaGetSymbolAddress(&p_wfc2,  g_wfc2_h);

    cudaFuncSetAttribute(attn_kernel, cudaFuncAttributeMaxDynamicSharedMemorySize,
                         SMEM_ATTN);
    cudaFuncSetAttribute(gemm_f16<false, false, true>,
                         cudaFuncAttributeMaxDynamicSharedMemorySize, SMEM_GEMM);
    cudaFuncSetAttribute(gemm_f16<false, true, false>,
                         cudaFuncAttributeMaxDynamicSharedMemorySize, SMEM_GEMM);
    cudaFuncSetAttribute(gemm_f16<true, false, true>,
                         cudaFuncAttributeMaxDynamicSharedMemorySize, SMEM_GEMM);
    cudaFuncSetAttribute(gemm_f16<false, false, false>,
                         cudaFuncAttributeMaxDynamicSharedMemorySize, SMEM_GEMM);

    prep_kernel<<<1, 256>>>(lscale, cpb_w1, cpb_b1, cpb_w2, q_bias, v_bias);
    rowmap_kernel<<<512, 256>>>();
    xgather_kernel<<<16384, 256>>>(x);
    wtrans_kernel<<<768,  256>>>(qkv_w,  (__half*)p_wqkv,  256, 768);
    wtrans_kernel<<<256,  256>>>(proj_w, (__half*)p_wproj, 256, 256);
    wtrans_kernel<<<1024, 256>>>(fc1_w,  (__half*)p_wfc1,  256, 1024);
    wtrans_kernel<<<1024, 256>>>(fc2_w,  (__half*)p_wfc2,  1024, 256);

    // qkv = xh @ qkv_w + qkv_bias  -> fp16
    gemm_f16<false, false, true><<<dim3(3, 1024), 256, SMEM_GEMM>>>(
        (const __half*)p_xh, (const __half*)p_wqkv, (const float*)p_qb,
        p_qkvh, 768, 256, nullptr);

    attn_kernel<<<2048, 256, SMEM_ATTN>>>((const __half*)p_qkvh, (__half*)p_attn);

    // y = scatter(attn @ proj_w + proj_b)
    gemm_f16<false, true, false><<<dim3(1, 1024), 256, SMEM_GEMM>>>(
        (const __half*)p_attn, (const __half*)p_wproj, proj_b,
        p_y, 256, 256, (const int*)p_rm);

    // x1 = x + LN(y)
    ln_add_kernel<true><<<MROWS / 8, 256>>>(x, (const float*)p_y, n1s, n1b,
                                            (float*)p_x1, (__half*)p_x1h);

    // h = gelu(x1 @ fc1_w + fc1_b)
    gemm_f16<true, false, true><<<dim3(4, 1024), 256, SMEM_GEMM>>>(
        (const __half*)p_x1h, (const __half*)p_wfc1, fc1_b,
        p_h, 1024, 256, nullptr);

    // h2 = h @ fc2_w + fc2_b
    gemm_f16<false, false, false><<<dim3(1, 1024), 256, SMEM_GEMM>>>(
        (const __half*)p_h, (const __half*)p_wfc2, fc2_b,
        p_h2, 256, 1024, nullptr);

    // out = x1 + LN(h2)
    ln_add_kernel<false><<<MROWS / 8, 256>>>((const float*)p_x1, (const float*)p_h2,
                                             n2s, n2b, out, nullptr);
}

// round 15
// speedup vs baseline: 1.1623x; 1.1623x over previous
#include <cuda_runtime.h>
#include <cuda_fp16.h>
#include <cstdint>

// ---------------------------------------------------------------------------
// SwinV2 block: B=32, H=W=64, C=256, NH=8, HD=32, WS=8, SS=4
// Round 15: round-13 GEMM config (best) + fp16 y/h2 to cut LN traffic.
// ---------------------------------------------------------------------------

static constexpr int SSc   = 4;
static constexpr int NTOK  = 64;
static constexpr int NHc   = 8;
static constexpr int Cc    = 256;
static constexpr int MROWS = 131072;
static constexpr int HIDc  = 1024;

__device__ __half g_qkvh[(size_t)MROWS * 768];
__device__ __half g_attn[(size_t)MROWS * Cc];
__device__ __half g_y   [(size_t)MROWS * Cc];      // fp16 now
__device__ float  g_x1  [(size_t)MROWS * Cc];
__device__ __half g_x1h [(size_t)MROWS * Cc];
__device__ __half g_h   [(size_t)MROWS * HIDc];
__device__ __half g_h2  [(size_t)MROWS * Cc];      // fp16 now
__device__ __half g_xh  [(size_t)MROWS * Cc];
__device__ float  g_rpb [NHc * NTOK * NTOK];
__device__ float  g_qkvbias[768];
__device__ float  g_hscale[NHc];
__device__ int    g_rowmap[MROWS];
__device__ __half g_wqkv_h[768 * 256];
__device__ __half g_wproj_h[256 * 256];
__device__ __half g_wfc1_h[1024 * 256];
__device__ __half g_wfc2_h[256 * 1024];

__device__ __forceinline__ float gelu_f(float x) {
    float x3 = x * x * x;
    return 0.5f * x * (1.f + tanhf(0.7978845608028654f * (x + 0.044715f * x3)));
}
__device__ __forceinline__ uint32_t smem_u32(const void* p) {
    uint32_t a;
    asm("{ .reg .u64 t; cvta.to.shared.u64 t, %1; cvt.u32.u64 %0, t; }" : "=r"(a) : "l"(p));
    return a;
}
__device__ __forceinline__ void mma_f16(float* c, const unsigned* a, const unsigned* b) {
    asm volatile(
        "mma.sync.aligned.m16n8k16.row.col.f32.f16.f16.f32 "
        "{%0,%1,%2,%3}, {%4,%5,%6,%7}, {%8,%9}, {%0,%1,%2,%3};"
        : "+f"(c[0]), "+f"(c[1]), "+f"(c[2]), "+f"(c[3])
        : "r"(a[0]), "r"(a[1]), "r"(a[2]), "r"(a[3]), "r"(b[0]), "r"(b[1]));
}
__device__ __forceinline__ void ldsm4(unsigned* r, uint32_t addr) {
    asm volatile("ldmatrix.sync.aligned.m8n8.x4.shared.b16 {%0,%1,%2,%3}, [%4];"
        : "=r"(r[0]), "=r"(r[1]), "=r"(r[2]), "=r"(r[3]) : "r"(addr));
}
__device__ __forceinline__ void ldsm4t(unsigned* r, uint32_t addr) {
    asm volatile("ldmatrix.sync.aligned.m8n8.x4.trans.shared.b16 {%0,%1,%2,%3}, [%4];"
        : "=r"(r[0]), "=r"(r[1]), "=r"(r[2]), "=r"(r[3]) : "r"(addr));
}
__device__ __forceinline__ void cp16(uint32_t dst, const void* src) {
    asm volatile("cp.async.cg.shared.global [%0], [%1], 16;" :: "r"(dst), "l"(src));
}
__device__ __forceinline__ unsigned pack_h2(float a, float b) {
    __half2 h = __floats2half2_rn(a, b);
    return *(unsigned*)&h;
}

// ---------------------------------------------------------------------------
__global__ void prep_kernel(const float* __restrict__ logit_scale,
                            const float* __restrict__ cpb_w1,
                            const float* __restrict__ cpb_b1,
                            const float* __restrict__ cpb_w2,
                            const float* __restrict__ q_bias,
                            const float* __restrict__ v_bias) {
    __shared__ float table[225][NHc];
    int t = threadIdx.x;
    for (int i = t; i < 768; i += 256) {
        float v = 0.f;
        if (i < 256)       v = q_bias[i];
        else if (i >= 512) v = v_bias[i - 512];
        g_qkvbias[i] = v;
    }
    if (t < NHc) {
        float ls = logit_scale[t];
        g_hscale[t] = expf(fminf(ls, 4.605170185988092f));
    }
    if (t < 225) {
        int a = t / 15, b = t % 15;
        float f0 = (float)(a - 7) * (8.f / 7.f);
        float f1 = (float)(b - 7) * (8.f / 7.f);
        f0 = copysignf(log2f(fabsf(f0) + 1.f) * (1.f / 3.f), f0);
        f1 = copysignf(log2f(fabsf(f1) + 1.f) * (1.f / 3.f), f1);
        float acc[NHc];
        #pragma unroll
        for (int h = 0; h < NHc; h++) acc[h] = 0.f;
        for (int j = 0; j < 512; j++) {
            float hid = f0 * cpb_w1[j] + f1 * cpb_w1[512 + j] + cpb_b1[j];
            hid = fmaxf(hid, 0.f);
            #pragma unroll
            for (int h = 0; h < NHc; h++) acc[h] += hid * cpb_w2[j * NHc + h];
        }
        #pragma unroll
        for (int h = 0; h < NHc; h++) table[t][h] = acc[h];
    }
    __syncthreads();
    for (int idx = t; idx < NHc * NTOK * NTOK; idx += 256) {
        int h = idx >> 12, rem = idx & 4095, i = rem >> 6, j = rem & 63;
        int iy = i >> 3, ix = i & 7, jy = j >> 3, jx = j & 7;
        int ti = (iy - jy + 7) * 15 + (ix - jx + 7);
        float v = table[ti][h];
        g_rpb[idx] = 16.f / (1.f + expf(-v));
    }
}

__global__ void rowmap_kernel() {
    int r = blockIdx.x * 256 + threadIdx.x;
    if (r >= MROWS) return;
    int b = r >> 12;
    int rem = r & 4095;
    int w = rem >> 6, n = rem & 63;
    int wy = w >> 3, wx = w & 7, ty = n >> 3, tx = n & 7;
    int hs = (wy * 8 + ty + SSc) & 63;
    int ws = (wx * 8 + tx + SSc) & 63;
    g_rowmap[r] = (b << 12) + (hs << 6) + ws;
}

__global__ void xgather_kernel(const float* __restrict__ x) {
    int idx = blockIdx.x * 256 + threadIdx.x;
    int base = idx << 3;
    int row = base >> 8, col = base & 255;
    int b = row >> 12, rem = row & 4095;
    int w = rem >> 6, n = rem & 63;
    int wy = w >> 3, wx = w & 7, ty = n >> 3, tx = n & 7;
    int hs = (wy * 8 + ty + SSc) & 63;
    int ws = (wx * 8 + tx + SSc) & 63;
    int src = (b << 12) + (hs << 6) + ws;
    const float* p = x + (size_t)src * 256 + col;
    float4 f0 = *(const float4*)p;
    float4 f1 = *(const float4*)(p + 4);
    uint4 u;
    u.x = pack_h2(f0.x, f0.y); u.y = pack_h2(f0.z, f0.w);
    u.z = pack_h2(f1.x, f1.y); u.w = pack_h2(f1.z, f1.w);
    *(uint4*)(g_xh + (size_t)row * 256 + col) = u;
}

__global__ void wtrans_kernel(const float* __restrict__ W, __half* __restrict__ Wt,
                              int K, int N) {
    int idx = blockIdx.x * 256 + threadIdx.x;
    if (idx >= K * N) return;
    int n = idx / K, k = idx - n * K;
    Wt[idx] = __float2half_rn(W[(size_t)k * N + n]);
}

// ---------------------------------------------------------------------------
// fp16 GEMM, BM=BN=128, BK=32, 3-stage cp.async pipeline (round-13 config).
// ---------------------------------------------------------------------------
static constexpr int G_STRIDE = 40;
static constexpr int G_STAGEB = 128 * G_STRIDE * 2;
static constexpr int SMEM_GEMM = 2 * 3 * G_STAGEB;   // 61440

template<bool GELU, bool SCATTER_C, bool OUT_HALF>
__global__ __launch_bounds__(256, 2)
void gemm_f16(const __half* __restrict__ A, const __half* __restrict__ Bt,
              const float* __restrict__ bias, void* __restrict__ Cm,
              int N, int K, const int* __restrict__ rowmap) {
    extern __shared__ __align__(16) unsigned char gsm[];
    __half* As = (__half*)gsm;
    __half* Bs = (__half*)(gsm + 3 * G_STAGEB);

    const int t = threadIdx.x;
    const int lane = t & 31, wid = t >> 5;
    const int wm = (wid >> 2) << 6;
    const int wn = (wid & 3) << 5;
    const int m0 = blockIdx.y * 128, n0 = blockIdx.x * 128;

    const int am = t >> 1;
    const int ak = (t & 1) << 4;
    const __half* ap = A  + (size_t)(m0 + am) * K + ak;
    const __half* bp = Bt + (size_t)(n0 + am) * K + ak;
    const uint32_t a_dst = smem_u32(As + am * G_STRIDE + ak);
    const uint32_t b_dst = smem_u32(Bs + am * G_STRIDE + ak);

    const int quad = lane >> 3, lr = lane & 7;
    const uint32_t a_addr0 = smem_u32(As + (wm + ((quad & 1) << 3) + lr) * G_STRIDE
                                         + ((quad >> 1) << 3));
    const uint32_t b_addr0 = smem_u32(Bs + (wn + ((quad >> 1) << 3) + lr) * G_STRIDE
                                         + ((quad & 1) << 3));
    const uint32_t MTB = 16 * G_STRIDE * 2;

    float acc[4][4][4];
    #pragma unroll
    for (int i = 0; i < 4; i++)
        #pragma unroll
        for (int j = 0; j < 4; j++)
            #pragma unroll
            for (int r = 0; r < 4; r++) acc[i][j][r] = 0.f;

    const int KT = K >> 5;

    cp16(a_dst, ap);           cp16(a_dst + 16, ap + 8);
    cp16(b_dst, bp);           cp16(b_dst + 16, bp + 8);
    asm volatile("cp.async.commit_group;" ::: "memory");
    cp16(a_dst + G_STAGEB, ap + 32);  cp16(a_dst + G_STAGEB + 16, ap + 40);
    cp16(b_dst + G_STAGEB, bp + 32);  cp16(b_dst + G_STAGEB + 16, bp + 40);
    asm volatile("cp.async.commit_group;" ::: "memory");

    int cur = 0;
    for (int kt = 0; kt < KT; kt++) {
        if (kt == KT - 1) asm volatile("cp.async.wait_group 0;" ::: "memory");
        else              asm volatile("cp.async.wait_group 1;" ::: "memory");
        __syncthreads();

        if (kt + 2 < KT) {
            int st = kt + 2;
            int sb = st - (st / 3) * 3;
            const __half* asrc = ap + st * 32;
            const __half* bsrc = bp + st * 32;
            cp16(a_dst + sb * G_STAGEB, asrc);
            cp16(a_dst + sb * G_STAGEB + 16, asrc + 8);
            cp16(b_dst + sb * G_STAGEB, bsrc);
            cp16(b_dst + sb * G_STAGEB + 16, bsrc + 8);
            asm volatile("cp.async.commit_group;" ::: "memory");
        }

        #pragma unroll
        for (int ks = 0; ks < 2; ks++) {
            const uint32_t ab = a_addr0 + cur * G_STAGEB + ks * 32;
            const uint32_t bb = b_addr0 + cur * G_STAGEB + ks * 32;
            unsigned af[4][4], b0[4], b1[4];
            #pragma unroll
            for (int mt = 0; mt < 4; mt++) ldsm4(af[mt], ab + mt * MTB);
            ldsm4(b0, bb);
            ldsm4(b1, bb + MTB);
            #pragma unroll
            for (int mt = 0; mt < 4; mt++) {
                mma_f16(acc[mt][0], af[mt], b0);
                mma_f16(acc[mt][1], af[mt], b0 + 2);
                mma_f16(acc[mt][2], af[mt], b1);
                mma_f16(acc[mt][3], af[mt], b1 + 2);
            }
        }

        if (++cur == 3) cur = 0;
    }

    float bv[4][2];
    #pragma unroll
    for (int nt = 0; nt < 4; nt++) {
        int c = n0 + wn + (nt << 3) + ((lane & 3) << 1);
        bv[nt][0] = bias[c];
        bv[nt][1] = bias[c + 1];
    }
    #pragma unroll
    for (int mt = 0; mt < 4; mt++) {
        int rr = m0 + wm + (mt << 4) + (lane >> 2);
        int r2 = rr + 8;
        int o1 = SCATTER_C ? rowmap[rr] : rr;
        int o2 = SCATTER_C ? rowmap[r2] : r2;
        #pragma unroll
        for (int nt = 0; nt < 4; nt++) {
            int c = n0 + wn + (nt << 3) + ((lane & 3) << 1);
            float2 v0, v1;
            v0.x = acc[mt][nt][0] + bv[nt][0];
            v0.y = acc[mt][nt][1] + bv[nt][1];
            v1.x = acc[mt][nt][2] + bv[nt][0];
            v1.y = acc[mt][nt][3] + bv[nt][1];
            if (GELU) {
                v0.x = gelu_f(v0.x); v0.y = gelu_f(v0.y);
                v1.x = gelu_f(v1.x); v1.y = gelu_f(v1.y);
            }
            if (OUT_HALF) {
                __half* C = (__half*)Cm;
                *(__half2*)(C + (size_t)o1 * N + c) = __floats2half2_rn(v0.x, v0.y);
                *(__half2*)(C + (size_t)o2 * N + c) = __floats2half2_rn(v1.x, v1.y);
            } else {
                float* C = (float*)Cm;
                *(float2*)(C + (size_t)o1 * N + c) = v0;
                *(float2*)(C + (size_t)o2 * N + c) = v1;
            }
        }
    }
}

// ---------------------------------------------------------------------------
// Tensorized windowed cosine attention (round-12 version).
// ---------------------------------------------------------------------------
static constexpr int BLOB_STRIDE = 776;
static constexpr int SMEM_ATTN = 64 * BLOB_STRIDE * 2 + 2 * 8 * 64 * 4 + 64 * 4;

__global__ __launch_bounds__(256)
void attn_kernel(const __half* __restrict__ qkv, __half* __restrict__ out) {
    extern __shared__ __align__(16) unsigned char dynsm[];
    __half* blob   = (__half*)dynsm;
    float*  invq_s = (float*)(dynsm + 64 * BLOB_STRIDE * 2);
    float*  invk_s = invq_s + 8 * 64;
    int*    lab    = (int*)(invk_s + 8 * 64);

    const int t = threadIdx.x, lane = t & 31, h = t >> 5;
    const int win = blockIdx.x;
    const __half* src = qkv + (size_t)win * 64 * 768;

    #pragma unroll
    for (int c = 0; c < 24; c++) {
        int chunk = c * 256 + t;
        int row = chunk / 96, off = (chunk - row * 96) << 3;
        cp16(smem_u32(blob + row * BLOB_STRIDE + off), src + row * 768 + off);
    }
    asm volatile("cp.async.commit_group;" ::: "memory");
    if (t < 64) {
        int w = win & 63;
        int wy = w >> 3, wx = w & 7, ty_ = t >> 3, tx_ = t & 7;
        int gh = wy * 8 + ty_, gw = wx * 8 + tx_;
        int rh = gh < 56 ? 0 : (gh < 60 ? 1 : 2);
        int rw = gw < 56 ? 0 : (gw < 60 ? 1 : 2);
        lab[t] = rh * 3 + rw;
    }
    asm volatile("cp.async.wait_group 0;" ::: "memory");
    __syncthreads();

    #pragma unroll
    for (int tk = lane; tk < 64; tk += 32) {
        const __half2* qp = (const __half2*)(blob + tk * BLOB_STRIDE + h * 32);
        const __half2* kp = (const __half2*)(blob + tk * BLOB_STRIDE + 256 + h * 32);
        float sq = 0.f, sk = 0.f;
        #pragma unroll
        for (int i = 0; i < 16; i++) {
            float2 f = __half22float2(qp[i]);
            sq += f.x * f.x + f.y * f.y;
            float2 g = __half22float2(kp[i]);
            sk += g.x * g.x + g.y * g.y;
        }
        invq_s[h * 64 + tk] = rsqrtf(fmaxf(sq, 1e-12f));
        invk_s[h * 64 + tk] = rsqrtf(fmaxf(sk, 1e-12f));
    }
    __syncwarp();

    const int quad = lane >> 3, lr = lane & 7;

    unsigned aS[4][2][4];
    #pragma unroll
    for (int mt = 0; mt < 4; mt++)
        #pragma unroll
        for (int kt = 0; kt < 2; kt++) {
            int row = mt * 16 + ((quad & 1) << 3) + lr;
            int col = h * 32 + kt * 16 + ((quad >> 1) << 3);
            ldsm4(aS[mt][kt], smem_u32(blob + row * BLOB_STRIDE + col));
        }

    float acc[4][8][4];
    #pragma unroll
    for (int mt = 0; mt < 4; mt++)
        #pragma unroll
        for (int nt = 0; nt < 8; nt++)
            #pragma unroll
            for (int r = 0; r < 4; r++) acc[mt][nt][r] = 0.f;
    #pragma unroll
    for (int np = 0; np < 4; np++)
        #pragma unroll
        for (int kt = 0; kt < 2; kt++) {
            int row = np * 16 + ((quad >> 1) << 3) + lr;
            int col = 256 + h * 32 + kt * 16 + ((quad & 1) << 3);
            unsigned bt[4];
            ldsm4(bt, smem_u32(blob + row * BLOB_STRIDE + col));
            #pragma unroll
            for (int mt = 0; mt < 4; mt++) {
                mma_f16(acc[mt][2 * np],     aS[mt][kt], bt);
                mma_f16(acc[mt][2 * np + 1], aS[mt][kt], bt + 2);
            }
        }

    const float sc = g_hscale[h];
    const float* rp = g_rpb + h * 4096;
    float ik0[8], ik1[8];
    int   cl0[8], cl1[8];
    #pragma unroll
    for (int nt = 0; nt < 8; nt++) {
        int c0 = nt * 8 + ((lane & 3) << 1);
        ik0[nt] = invk_s[h * 64 + c0];
        ik1[nt] = invk_s[h * 64 + c0 + 1];
        cl0[nt] = lab[c0];
        cl1[nt] = lab[c0 + 1];
    }
    #pragma unroll
    for (int mt = 0; mt < 4; mt++) {
        int r0 = mt * 16 + (lane >> 2), r1 = r0 + 8;
        float f0 = sc * invq_s[h * 64 + r0];
        float f1 = sc * invq_s[h * 64 + r1];
        int l0 = lab[r0], l1 = lab[r1];
        #pragma unroll
        for (int nt = 0; nt < 8; nt++) {
            int c0 = nt * 8 + ((lane & 3) << 1);
            float rp00 = __ldg(rp + r0 * 64 + c0), rp01 = __ldg(rp + r0 * 64 + c0 + 1);
            float rp10 = __ldg(rp + r1 * 64 + c0), rp11 = __ldg(rp + r1 * 64 + c0 + 1);
            acc[mt][nt][0] = acc[mt][nt][0] * f0 * ik0[nt] + rp00 + (l0 == cl0[nt] ? 0.f : -100.f);
            acc[mt][nt][1] = acc[mt][nt][1] * f0 * ik1[nt] + rp01 + (l0 == cl1[nt] ? 0.f : -100.f);
            acc[mt][nt][2] = acc[mt][nt][2] * f1 * ik0[nt] + rp10 + (l1 == cl0[nt] ? 0.f : -100.f);
            acc[mt][nt][3] = acc[mt][nt][3] * f1 * ik1[nt] + rp11 + (l1 == cl1[nt] ? 0.f : -100.f);
        }
        float m0 = -1e30f, m1 = -1e30f;
        #pragma unroll
        for (int nt = 0; nt < 8; nt++) {
            m0 = fmaxf(m0, fmaxf(acc[mt][nt][0], acc[mt][nt][1]));
            m1 = fmaxf(m1, fmaxf(acc[mt][nt][2], acc[mt][nt][3]));
        }
        m0 = fmaxf(m0, __shfl_xor_sync(0xffffffffu, m0, 1));
        m0 = fmaxf(m0, __shfl_xor_sync(0xffffffffu, m0, 2));
        m1 = fmaxf(m1, __shfl_xor_sync(0xffffffffu, m1, 1));
        m1 = fmaxf(m1, __shfl_xor_sync(0xffffffffu, m1, 2));
        float s0 = 0.f, s1 = 0.f;
        #pragma unroll
        for (int nt = 0; nt < 8; nt++) {
            acc[mt][nt][0] = __expf(acc[mt][nt][0] - m0); s0 += acc[mt][nt][0];
            acc[mt][nt][1] = __expf(acc[mt][nt][1] - m0); s0 += acc[mt][nt][1];
            acc[mt][nt][2] = __expf(acc[mt][nt][2] - m1); s1 += acc[mt][nt][2];
            acc[mt][nt][3] = __expf(acc[mt][nt][3] - m1); s1 += acc[mt][nt][3];
        }
        s0 += __shfl_xor_sync(0xffffffffu, s0, 1);
        s0 += __shfl_xor_sync(0xffffffffu, s0, 2);
        s1 += __shfl_xor_sync(0xffffffffu, s1, 1);
        s1 += __shfl_xor_sync(0xffffffffu, s1, 2);
        float i0 = 1.f / s0, i1 = 1.f / s1;
        #pragma unroll
        for (int nt = 0; nt < 8; nt++) {
            acc[mt][nt][0] *= i0; acc[mt][nt][1] *= i0;
            acc[mt][nt][2] *= i1; acc[mt][nt][3] *= i1;
        }
    }

    unsigned pf[4][4][4];
    #pragma unroll
    for (int mt = 0; mt < 4; mt++)
        #pragma unroll
        for (int kt = 0; kt < 4; kt++) {
            pf[mt][kt][0] = pack_h2(acc[mt][2 * kt][0],     acc[mt][2 * kt][1]);
            pf[mt][kt][1] = pack_h2(acc[mt][2 * kt][2],     acc[mt][2 * kt][3]);
            pf[mt][kt][2] = pack_h2(acc[mt][2 * kt + 1][0], acc[mt][2 * kt + 1][1]);
            pf[mt][kt][3] = pack_h2(acc[mt][2 * kt + 1][2], acc[mt][2 * kt + 1][3]);
        }

    float O[4][4][4];
    #pragma unroll
    for (int mt = 0; mt < 4; mt++)
        #pragma unroll
        for (int nt = 0; nt < 4; nt++)
            #pragma unroll
            for (int r = 0; r < 4; r++) O[mt][nt][r] = 0.f;
    #pragma unroll
    for (int kt = 0; kt < 4; kt++)
        #pragma unroll
        for (int np = 0; np < 2; np++) {
            int row = kt * 16 + ((quad & 1) << 3) + lr;
            int col = 512 + h * 32 + np * 16 + ((quad >> 1) << 3);
            unsigned bt[4];
            ldsm4t(bt, smem_u32(blob + row * BLOB_STRIDE + col));
            #pragma unroll
            for (int mt = 0; mt < 4; mt++) {
                mma_f16(O[mt][2 * np],     pf[mt][kt], bt);
                mma_f16(O[mt][2 * np + 1], pf[mt][kt], bt + 2);
            }
        }

    #pragma unroll
    for (int mt = 0; mt < 4; mt++) {
        int r0 = mt * 16 + (lane >> 2);
        #pragma unroll
        for (int nt = 0; nt < 4; nt++) {
            int c0 = nt * 8 + ((lane & 3) << 1);
            __half* op = out + (size_t)(win * 64 + r0) * 256 + h * 32 + c0;
            *(__half2*)op = __floats2half2_rn(O[mt][nt][0], O[mt][nt][1]);
            *(__half2*)(op + 8 * 256) = __floats2half2_rn(O[mt][nt][2], O[mt][nt][3]);
        }
    }
}

// ---------------------------------------------------------------------------
// out = resid + LayerNorm(y)*sc + bi ; y is fp16; optional fp16 mirror out.
// ---------------------------------------------------------------------------
template<bool WRITE_H>
__global__ __launch_bounds__(256)
void ln_add_kernel(const float* __restrict__ resid, const __half* __restrict__ y,
                   const float* __restrict__ sc, const float* __restrict__ bi,
                   float* __restrict__ out, __half* __restrict__ outh) {
    int warp = (blockIdx.x * 256 + threadIdx.x) >> 5;
    int lane = threadIdx.x & 31;
    if (warp >= MROWS) return;
    const __half* yr = y + (size_t)warp * 256;
    uint4 uy = *(const uint4*)(yr + lane * 8);
    float v[8];
    {
        __half2* hp = (__half2*)&uy;
        #pragma unroll
        for (int i = 0; i < 4; i++) {
            float2 f = __half22float2(hp[i]);
            v[2 * i] = f.x; v[2 * i + 1] = f.y;
        }
    }
    float s = 0.f;
    #pragma unroll
    for (int i = 0; i < 8; i++) s += v[i];
    #pragma unroll
    for (int o = 16; o > 0; o >>= 1) s += __shfl_xor_sync(0xffffffffu, s, o);
    float mean = s * (1.f / 256.f);
    float sq = 0.f;
    #pragma unroll
    for (int i = 0; i < 8; i++) { float d = v[i] - mean; sq += d * d; }
    #pragma unroll
    for (int o = 16; o > 0; o >>= 1) sq += __shfl_xor_sync(0xffffffffu, sq, o);
    float rstd = rsqrtf(sq * (1.f / 256.f) + 1e-6f);
    const float* rr = resid + (size_t)warp * 256;
    float* op = out + (size_t)warp * 256;
    float ov[8];
    #pragma unroll
    for (int i = 0; i < 8; i++) {
        int c = lane * 8 + i;
        ov[i] = rr[c] + (v[i] - mean) * rstd * sc[c] + bi[c];
        op[c] = ov[i];
    }
    if (WRITE_H) {
        uint4 u;
        u.x = pack_h2(ov[0], ov[1]); u.y = pack_h2(ov[2], ov[3]);
        u.z = pack_h2(ov[4], ov[5]); u.w = pack_h2(ov[6], ov[7]);
        *(uint4*)(outh + (size_t)warp * 256 + lane * 8) = u;
    }
}

// ---------------------------------------------------------------------------
extern "C" void kernel_launch(void* const* d_in, const int* in_sizes, int n_in,
                              void* d_out, int out_size) {
    const float* x       = (const float*)d_in[0];
    const float* qkv_w   = (const float*)d_in[1];
    const float* q_bias  = (const float*)d_in[2];
    const float* v_bias  = (const float*)d_in[3];
    const float* lscale  = (const float*)d_in[4];
    const float* cpb_w1  = (const float*)d_in[5];
    const float* cpb_b1  = (const float*)d_in[6];
    const float* cpb_w2  = (const float*)d_in[7];
    const float* proj_w  = (const float*)d_in[8];
    const float* proj_b  = (const float*)d_in[9];
    const float* n1s     = (const float*)d_in[10];
    const float* n1b     = (const float*)d_in[11];
    const float* n2s     = (const float*)d_in[12];
    const float* n2b     = (const float*)d_in[13];
    const float* fc1_w   = (const float*)d_in[14];
    const float* fc1_b   = (const float*)d_in[15];
    const float* fc2_w   = (const float*)d_in[16];
    const float* fc2_b   = (const float*)d_in[17];
    float* out = (float*)d_out;

    void *p_qkvh, *p_attn, *p_y, *p_x1, *p_x1h, *p_h, *p_h2, *p_xh, *p_qb, *p_rm;
    void *p_wqkv, *p_wproj, *p_wfc1, *p_wfc2;
    cudaGetSymbolAddress(&p_qkvh, g_qkvh);
    cudaGetSymbolAddress(&p_attn, g_attn);
    cudaGetSymbolAddress(&p_y,    g_y);
    cudaGetSymbolAddress(&p_x1,   g_x1);
    cudaGetSymbolAddress(&p_x1h,  g_x1h);
    cudaGetSymbolAddress(&p_h,    g_h);
    cudaGetSymbolAddress(&p_h2,   g_h2);
    cudaGetSymbolAddress(&p_xh,   g_xh);
    cudaGetSymbolAddress(&p_qb,   g_qkvbias);
    cudaGetSymbolAddress(&p_rm,   g_rowmap);
    cudaGetSymbolAddress(&p_wqkv,  g_wqkv_h);
    cudaGetSymbolAddress(&p_wproj, g_wproj_h);
    cudaGetSymbolAddress(&p_wfc1,  g_wfc1_h);
    cudaGetSymbolAddress(&p_wfc2,  g_wfc2_h);

    cudaFuncSetAttribute(attn_kernel, cudaFuncAttributeMaxDynamicSharedMemorySize,
                         SMEM_ATTN);
    cudaFuncSetAttribute(gemm_f16<false, false, true>,
                         cudaFuncAttributeMaxDynamicSharedMemorySize, SMEM_GEMM);
    cudaFuncSetAttribute(gemm_f16<false, true, true>,
                         cudaFuncAttributeMaxDynamicSharedMemorySize, SMEM_GEMM);
    cudaFuncSetAttribute(gemm_f16<true, false, true>,
                         cudaFuncAttributeMaxDynamicSharedMemorySize, SMEM_GEMM);
    cudaFuncSetAttribute(gemm_f16<false, false, false>,
                         cudaFuncAttributeMaxDynamicSharedMemorySize, SMEM_GEMM);

    prep_kernel<<<1, 256>>>(lscale, cpb_w1, cpb_b1, cpb_w2, q_bias, v_bias);
    rowmap_kernel<<<512, 256>>>();
    xgather_kernel<<<16384, 256>>>(x);
    wtrans_kernel<<<768,  256>>>(qkv_w,  (__half*)p_wqkv,  256, 768);
    wtrans_kernel<<<256,  256>>>(proj_w, (__half*)p_wproj, 256, 256);
    wtrans_kernel<<<1024, 256>>>(fc1_w,  (__half*)p_wfc1,  256, 1024);
    wtrans_kernel<<<1024, 256>>>(fc2_w,  (__half*)p_wfc2,  1024, 256);

    // qkv = xh @ qkv_w + qkv_bias  -> fp16
    gemm_f16<false, false, true><<<dim3(6, 1024), 256, SMEM_GEMM>>>(
        (const __half*)p_xh, (const __half*)p_wqkv, (const float*)p_qb,
        p_qkvh, 768, 256, nullptr);

    attn_kernel<<<2048, 256, SMEM_ATTN>>>((const __half*)p_qkvh, (__half*)p_attn);

    // y = scatter(attn @ proj_w + proj_b)  -> fp16
    gemm_f16<false, true, true><<<dim3(2, 1024), 256, SMEM_GEMM>>>(
        (const __half*)p_attn, (const __half*)p_wproj, proj_b,
        p_y, 256, 256, (const int*)p_rm);

    // x1 = x + LN(y)  (fp32 + fp16 mirror)
    ln_add_kernel<true><<<MROWS / 8, 256>>>(x, (const __half*)p_y, n1s, n1b,
                                            (float*)p_x1, (__half*)p_x1h);

    // h = gelu(x1 @ fc1_w + fc1_b)  -> fp16
    gemm_f16<true, false, true><<<dim3(8, 1024), 256, SMEM_GEMM>>>(
        (const __half*)p_x1h, (const __half*)p_wfc1, fc1_b,
        p_h, 1024, 256, nullptr);

    // h2 = h @ fc2_w + fc2_b  -> fp16
    gemm_f16<false, false, true><<<dim3(2, 1024), 256, SMEM_GEMM>>>(
        (const __half*)p_h, (const __half*)p_wfc2, fc2_b,
        p_h2, 256, 1024, nullptr);

    // out = x1 + LN(h2)
    ln_add_kernel<false><<<MROWS / 8, 256>>>((const float*)p_x1, (const __half*)p_h2,
                                             n2s, n2b, out, nullptr);
}

// round 16
// speedup vs baseline: 1.2510x; 1.0763x over previous
#include <cuda_runtime.h>
#include <cuda_fp16.h>
#include <cstdint>

// ---------------------------------------------------------------------------
// SwinV2 block: B=32, H=W=64, C=256, NH=8, HD=32, WS=8, SS=4
// Round 16: drop fp32 x1 (fp16 residual chain), float2 rpb loads in attention.
// ---------------------------------------------------------------------------

static constexpr int SSc   = 4;
static constexpr int NTOK  = 64;
static constexpr int NHc   = 8;
static constexpr int Cc    = 256;
static constexpr int MROWS = 131072;
static constexpr int HIDc  = 1024;

__device__ __half g_qkvh[(size_t)MROWS * 768];
__device__ __half g_attn[(size_t)MROWS * Cc];
__device__ __half g_y   [(size_t)MROWS * Cc];
__device__ __half g_x1h [(size_t)MROWS * Cc];      // sole x1 representation
__device__ __half g_h   [(size_t)MROWS * HIDc];
__device__ __half g_h2  [(size_t)MROWS * Cc];
__device__ __half g_xh  [(size_t)MROWS * Cc];
__device__ float  g_rpb [NHc * NTOK * NTOK];
__device__ float  g_qkvbias[768];
__device__ float  g_hscale[NHc];
__device__ int    g_rowmap[MROWS];
__device__ __half g_wqkv_h[768 * 256];
__device__ __half g_wproj_h[256 * 256];
__device__ __half g_wfc1_h[1024 * 256];
__device__ __half g_wfc2_h[256 * 1024];

__device__ __forceinline__ float gelu_f(float x) {
    float x3 = x * x * x;
    return 0.5f * x * (1.f + tanhf(0.7978845608028654f * (x + 0.044715f * x3)));
}
__device__ __forceinline__ uint32_t smem_u32(const void* p) {
    uint32_t a;
    asm("{ .reg .u64 t; cvta.to.shared.u64 t, %1; cvt.u32.u64 %0, t; }" : "=r"(a) : "l"(p));
    return a;
}
__device__ __forceinline__ void mma_f16(float* c, const unsigned* a, const unsigned* b) {
    asm volatile(
        "mma.sync.aligned.m16n8k16.row.col.f32.f16.f16.f32 "
        "{%0,%1,%2,%3}, {%4,%5,%6,%7}, {%8,%9}, {%0,%1,%2,%3};"
        : "+f"(c[0]), "+f"(c[1]), "+f"(c[2]), "+f"(c[3])
        : "r"(a[0]), "r"(a[1]), "r"(a[2]), "r"(a[3]), "r"(b[0]), "r"(b[1]));
}
__device__ __forceinline__ void ldsm4(unsigned* r, uint32_t addr) {
    asm volatile("ldmatrix.sync.aligned.m8n8.x4.shared.b16 {%0,%1,%2,%3}, [%4];"
        : "=r"(r[0]), "=r"(r[1]), "=r"(r[2]), "=r"(r[3]) : "r"(addr));
}
__device__ __forceinline__ void ldsm4t(unsigned* r, uint32_t addr) {
    asm volatile("ldmatrix.sync.aligned.m8n8.x4.trans.shared.b16 {%0,%1,%2,%3}, [%4];"
        : "=r"(r[0]), "=r"(r[1]), "=r"(r[2]), "=r"(r[3]) : "r"(addr));
}
__device__ __forceinline__ void cp16(uint32_t dst, const void* src) {
    asm volatile("cp.async.cg.shared.global [%0], [%1], 16;" :: "r"(dst), "l"(src));
}
__device__ __forceinline__ unsigned pack_h2(float a, float b) {
    __half2 h = __floats2half2_rn(a, b);
    return *(unsigned*)&h;
}

// ---------------------------------------------------------------------------
__global__ void prep_kernel(const float* __restrict__ logit_scale,
                            const float* __restrict__ cpb_w1,
                            const float* __restrict__ cpb_b1,
                            const float* __restrict__ cpb_w2,
                            const float* __restrict__ q_bias,
                            const float* __restrict__ v_bias) {
    __shared__ float table[225][NHc];
    int t = threadIdx.x;
    for (int i = t; i < 768; i += 256) {
        float v = 0.f;
        if (i < 256)       v = q_bias[i];
        else if (i >= 512) v = v_bias[i - 512];
        g_qkvbias[i] = v;
    }
    if (t < NHc) {
        float ls = logit_scale[t];
        g_hscale[t] = expf(fminf(ls, 4.605170185988092f));
    }
    if (t < 225) {
        int a = t / 15, b = t % 15;
        float f0 = (float)(a - 7) * (8.f / 7.f);
        float f1 = (float)(b - 7) * (8.f / 7.f);
        f0 = copysignf(log2f(fabsf(f0) + 1.f) * (1.f / 3.f), f0);
        f1 = copysignf(log2f(fabsf(f1) + 1.f) * (1.f / 3.f), f1);
        float acc[NHc];
        #pragma unroll
        for (int h = 0; h < NHc; h++) acc[h] = 0.f;
        for (int j = 0; j < 512; j++) {
            float hid = f0 * cpb_w1[j] + f1 * cpb_w1[512 + j] + cpb_b1[j];
            hid = fmaxf(hid, 0.f);
            #pragma unroll
            for (int h = 0; h < NHc; h++) acc[h] += hid * cpb_w2[j * NHc + h];
        }
        #pragma unroll
        for (int h = 0; h < NHc; h++) table[t][h] = acc[h];
    }
    __syncthreads();
    for (int idx = t; idx < NHc * NTOK * NTOK; idx += 256) {
        int h = idx >> 12, rem = idx & 4095, i = rem >> 6, j = rem & 63;
        int iy = i >> 3, ix = i & 7, jy = j >> 3, jx = j & 7;
        int ti = (iy - jy + 7) * 15 + (ix - jx + 7);
        float v = table[ti][h];
        g_rpb[idx] = 16.f / (1.f + expf(-v));
    }
}

__global__ void rowmap_kernel() {
    int r = blockIdx.x * 256 + threadIdx.x;
    if (r >= MROWS) return;
    int b = r >> 12;
    int rem = r & 4095;
    int w = rem >> 6, n = rem & 63;
    int wy = w >> 3, wx = w & 7, ty = n >> 3, tx = n & 7;
    int hs = (wy * 8 + ty + SSc) & 63;
    int ws = (wx * 8 + tx + SSc) & 63;
    g_rowmap[r] = (b << 12) + (hs << 6) + ws;
}

__global__ void xgather_kernel(const float* __restrict__ x) {
    int idx = blockIdx.x * 256 + threadIdx.x;
    int base = idx << 3;
    int row = base >> 8, col = base & 255;
    int b = row >> 12, rem = row & 4095;
    int w = rem >> 6, n = rem & 63;
    int wy = w >> 3, wx = w & 7, ty = n >> 3, tx = n & 7;
    int hs = (wy * 8 + ty + SSc) & 63;
    int ws = (wx * 8 + tx + SSc) & 63;
    int src = (b << 12) + (hs << 6) + ws;
    const float* p = x + (size_t)src * 256 + col;
    float4 f0 = *(const float4*)p;
    float4 f1 = *(const float4*)(p + 4);
    uint4 u;
    u.x = pack_h2(f0.x, f0.y); u.y = pack_h2(f0.z, f0.w);
    u.z = pack_h2(f1.x, f1.y); u.w = pack_h2(f1.z, f1.w);
    *(uint4*)(g_xh + (size_t)row * 256 + col) = u;
}

__global__ void wtrans_kernel(const float* __restrict__ W, __half* __restrict__ Wt,
                              int K, int N) {
    int idx = blockIdx.x * 256 + threadIdx.x;
    if (idx >= K * N) return;
    int n = idx / K, k = idx - n * K;
    Wt[idx] = __float2half_rn(W[(size_t)k * N + n]);
}

// ---------------------------------------------------------------------------
// fp16 GEMM, BM=BN=128, BK=32, 3-stage cp.async pipeline (round-13 config).
// ---------------------------------------------------------------------------
static constexpr int G_STRIDE = 40;
static constexpr int G_STAGEB = 128 * G_STRIDE * 2;
static constexpr int SMEM_GEMM = 2 * 3 * G_STAGEB;   // 61440

template<bool GELU, bool SCATTER_C, bool OUT_HALF>
__global__ __launch_bounds__(256, 2)
void gemm_f16(const __half* __restrict__ A, const __half* __restrict__ Bt,
              const float* __restrict__ bias, void* __restrict__ Cm,
              int N, int K, const int* __restrict__ rowmap) {
    extern __shared__ __align__(16) unsigned char gsm[];
    __half* As = (__half*)gsm;
    __half* Bs = (__half*)(gsm + 3 * G_STAGEB);

    const int t = threadIdx.x;
    const int lane = t & 31, wid = t >> 5;
    const int wm = (wid >> 2) << 6;
    const int wn = (wid & 3) << 5;
    const int m0 = blockIdx.y * 128, n0 = blockIdx.x * 128;

    const int am = t >> 1;
    const int ak = (t & 1) << 4;
    const __half* ap = A  + (size_t)(m0 + am) * K + ak;
    const __half* bp = Bt + (size_t)(n0 + am) * K + ak;
    const uint32_t a_dst = smem_u32(As + am * G_STRIDE + ak);
    const uint32_t b_dst = smem_u32(Bs + am * G_STRIDE + ak);

    const int quad = lane >> 3, lr = lane & 7;
    const uint32_t a_addr0 = smem_u32(As + (wm + ((quad & 1) << 3) + lr) * G_STRIDE
                                         + ((quad >> 1) << 3));
    const uint32_t b_addr0 = smem_u32(Bs + (wn + ((quad >> 1) << 3) + lr) * G_STRIDE
                                         + ((quad & 1) << 3));
    const uint32_t MTB = 16 * G_STRIDE * 2;

    float acc[4][4][4];
    #pragma unroll
    for (int i = 0; i < 4; i++)
        #pragma unroll
        for (int j = 0; j < 4; j++)
            #pragma unroll
            for (int r = 0; r < 4; r++) acc[i][j][r] = 0.f;

    const int KT = K >> 5;

    cp16(a_dst, ap);           cp16(a_dst + 16, ap + 8);
    cp16(b_dst, bp);           cp16(b_dst + 16, bp + 8);
    asm volatile("cp.async.commit_group;" ::: "memory");
    cp16(a_dst + G_STAGEB, ap + 32);  cp16(a_dst + G_STAGEB + 16, ap + 40);
    cp16(b_dst + G_STAGEB, bp + 32);  cp16(b_dst + G_STAGEB + 16, bp + 40);
    asm volatile("cp.async.commit_group;" ::: "memory");

    int cur = 0;
    for (int kt = 0; kt < KT; kt++) {
        if (kt == KT - 1) asm volatile("cp.async.wait_group 0;" ::: "memory");
        else              asm volatile("cp.async.wait_group 1;" ::: "memory");
        __syncthreads();

        if (kt + 2 < KT) {
            int st = kt + 2;
            int sb = st - (st / 3) * 3;
            const __half* asrc = ap + st * 32;
            const __half* bsrc = bp + st * 32;
            cp16(a_dst + sb * G_STAGEB, asrc);
            cp16(a_dst + sb * G_STAGEB + 16, asrc + 8);
            cp16(b_dst + sb * G_STAGEB, bsrc);
            cp16(b_dst + sb * G_STAGEB + 16, bsrc + 8);
            asm volatile("cp.async.commit_group;" ::: "memory");
        }

        #pragma unroll
        for (int ks = 0; ks < 2; ks++) {
            const uint32_t ab = a_addr0 + cur * G_STAGEB + ks * 32;
            const uint32_t bb = b_addr0 + cur * G_STAGEB + ks * 32;
            unsigned af[4][4], b0[4], b1[4];
            #pragma unroll
            for (int mt = 0; mt < 4; mt++) ldsm4(af[mt], ab + mt * MTB);
            ldsm4(b0, bb);
            ldsm4(b1, bb + MTB);
            #pragma unroll
            for (int mt = 0; mt < 4; mt++) {
                mma_f16(acc[mt][0], af[mt], b0);
                mma_f16(acc[mt][1], af[mt], b0 + 2);
                mma_f16(acc[mt][2], af[mt], b1);
                mma_f16(acc[mt][3], af[mt], b1 + 2);
            }
        }

        if (++cur == 3) cur = 0;
    }

    float bv[4][2];
    #pragma unroll
    for (int nt = 0; nt < 4; nt++) {
        int c = n0 + wn + (nt << 3) + ((lane & 3) << 1);
        bv[nt][0] = bias[c];
        bv[nt][1] = bias[c + 1];
    }
    #pragma unroll
    for (int mt = 0; mt < 4; mt++) {
        int rr = m0 + wm + (mt << 4) + (lane >> 2);
        int r2 = rr + 8;
        int o1 = SCATTER_C ? rowmap[rr] : rr;
        int o2 = SCATTER_C ? rowmap[r2] : r2;
        #pragma unroll
        for (int nt = 0; nt < 4; nt++) {
            int c = n0 + wn + (nt << 3) + ((lane & 3) << 1);
            float2 v0, v1;
            v0.x = acc[mt][nt][0] + bv[nt][0];
            v0.y = acc[mt][nt][1] + bv[nt][1];
            v1.x = acc[mt][nt][2] + bv[nt][0];
            v1.y = acc[mt][nt][3] + bv[nt][1];
            if (GELU) {
                v0.x = gelu_f(v0.x); v0.y = gelu_f(v0.y);
                v1.x = gelu_f(v1.x); v1.y = gelu_f(v1.y);
            }
            if (OUT_HALF) {
                __half* C = (__half*)Cm;
                *(__half2*)(C + (size_t)o1 * N + c) = __floats2half2_rn(v0.x, v0.y);
                *(__half2*)(C + (size_t)o2 * N + c) = __floats2half2_rn(v1.x, v1.y);
            } else {
                float* C = (float*)Cm;
                *(float2*)(C + (size_t)o1 * N + c) = v0;
                *(float2*)(C + (size_t)o2 * N + c) = v1;
            }
        }
    }
}

// ---------------------------------------------------------------------------
// Tensorized windowed cosine attention (float2 rpb loads).
// ---------------------------------------------------------------------------
static constexpr int BLOB_STRIDE = 776;
static constexpr int SMEM_ATTN = 64 * BLOB_STRIDE * 2 + 2 * 8 * 64 * 4 + 64 * 4;

__global__ __launch_bounds__(256)
void attn_kernel(const __half* __restrict__ qkv, __half* __restrict__ out) {
    extern __shared__ __align__(16) unsigned char dynsm[];
    __half* blob   = (__half*)dynsm;
    float*  invq_s = (float*)(dynsm + 64 * BLOB_STRIDE * 2);
    float*  invk_s = invq_s + 8 * 64;
    int*    lab    = (int*)(invk_s + 8 * 64);

    const int t = threadIdx.x, lane = t & 31, h = t >> 5;
    const int win = blockIdx.x;
    const __half* src = qkv + (size_t)win * 64 * 768;

    #pragma unroll
    for (int c = 0; c < 24; c++) {
        int chunk = c * 256 + t;
        int row = chunk / 96, off = (chunk - row * 96) << 3;
        cp16(smem_u32(blob + row * BLOB_STRIDE + off), src + row * 768 + off);
    }
    asm volatile("cp.async.commit_group;" ::: "memory");
    if (t < 64) {
        int w = win & 63;
        int wy = w >> 3, wx = w & 7, ty_ = t >> 3, tx_ = t & 7;
        int gh = wy * 8 + ty_, gw = wx * 8 + tx_;
        int rh = gh < 56 ? 0 : (gh < 60 ? 1 : 2);
        int rw = gw < 56 ? 0 : (gw < 60 ? 1 : 2);
        lab[t] = rh * 3 + rw;
    }
    asm volatile("cp.async.wait_group 0;" ::: "memory");
    __syncthreads();

    #pragma unroll
    for (int tk = lane; tk < 64; tk += 32) {
        const __half2* qp = (const __half2*)(blob + tk * BLOB_STRIDE + h * 32);
        const __half2* kp = (const __half2*)(blob + tk * BLOB_STRIDE + 256 + h * 32);
        float sq = 0.f, sk = 0.f;
        #pragma unroll
        for (int i = 0; i < 16; i++) {
            float2 f = __half22float2(qp[i]);
            sq += f.x * f.x + f.y * f.y;
            float2 g = __half22float2(kp[i]);
            sk += g.x * g.x + g.y * g.y;
        }
        invq_s[h * 64 + tk] = rsqrtf(fmaxf(sq, 1e-12f));
        invk_s[h * 64 + tk] = rsqrtf(fmaxf(sk, 1e-12f));
    }
    __syncwarp();

    const int quad = lane >> 3, lr = lane & 7;

    unsigned aS[4][2][4];
    #pragma unroll
    for (int mt = 0; mt < 4; mt++)
        #pragma unroll
        for (int kt = 0; kt < 2; kt++) {
            int row = mt * 16 + ((quad & 1) << 3) + lr;
            int col = h * 32 + kt * 16 + ((quad >> 1) << 3);
            ldsm4(aS[mt][kt], smem_u32(blob + row * BLOB_STRIDE + col));
        }

    float acc[4][8][4];
    #pragma unroll
    for (int mt = 0; mt < 4; mt++)
        #pragma unroll
        for (int nt = 0; nt < 8; nt++)
            #pragma unroll
            for (int r = 0; r < 4; r++) acc[mt][nt][r] = 0.f;
    #pragma unroll
    for (int np = 0; np < 4; np++)
        #pragma unroll
        for (int kt = 0; kt < 2; kt++) {
            int row = np * 16 + ((quad >> 1) << 3) + lr;
            int col = 256 + h * 32 + kt * 16 + ((quad & 1) << 3);
            unsigned bt[4];
            ldsm4(bt, smem_u32(blob + row * BLOB_STRIDE + col));
            #pragma unroll
            for (int mt = 0; mt < 4; mt++) {
                mma_f16(acc[mt][2 * np],     aS[mt][kt], bt);
                mma_f16(acc[mt][2 * np + 1], aS[mt][kt], bt + 2);
            }
        }

    const float sc = g_hscale[h];
    const float* rp = g_rpb + h * 4096;
    float ik0[8], ik1[8];
    int   cl0[8], cl1[8];
    #pragma unroll
    for (int nt = 0; nt < 8; nt++) {
        int c0 = nt * 8 + ((lane & 3) << 1);
        ik0[nt] = invk_s[h * 64 + c0];
        ik1[nt] = invk_s[h * 64 + c0 + 1];
        cl0[nt] = lab[c0];
        cl1[nt] = lab[c0 + 1];
    }
    #pragma unroll
    for (int mt = 0; mt < 4; mt++) {
        int r0 = mt * 16 + (lane >> 2), r1 = r0 + 8;
        float f0 = sc * invq_s[h * 64 + r0];
        float f1 = sc * invq_s[h * 64 + r1];
        int l0 = lab[r0], l1 = lab[r1];
        #pragma unroll
        for (int nt = 0; nt < 8; nt++) {
            int c0 = nt * 8 + ((lane & 3) << 1);
            float2 rpa = *(const float2*)(rp + r0 * 64 + c0);
            float2 rpb = *(const float2*)(rp + r1 * 64 + c0);
            acc[mt][nt][0] = acc[mt][nt][0] * f0 * ik0[nt] + rpa.x + (l0 == cl0[nt] ? 0.f : -100.f);
            acc[mt][nt][1] = acc[mt][nt][1] * f0 * ik1[nt] + rpa.y + (l0 == cl1[nt] ? 0.f : -100.f);
            acc[mt][nt][2] = acc[mt][nt][2] * f1 * ik0[nt] + rpb.x + (l1 == cl0[nt] ? 0.f : -100.f);
            acc[mt][nt][3] = acc[mt][nt][3] * f1 * ik1[nt] + rpb.y + (l1 == cl1[nt] ? 0.f : -100.f);
        }
        float m0 = -1e30f, m1 = -1e30f;
        #pragma unroll
        for (int nt = 0; nt < 8; nt++) {
            m0 = fmaxf(m0, fmaxf(acc[mt][nt][0], acc[mt][nt][1]));
            m1 = fmaxf(m1, fmaxf(acc[mt][nt][2], acc[mt][nt][3]));
        }
        m0 = fmaxf(m0, __shfl_xor_sync(0xffffffffu, m0, 1));
        m0 = fmaxf(m0, __shfl_xor_sync(0xffffffffu, m0, 2));
        m1 = fmaxf(m1, __shfl_xor_sync(0xffffffffu, m1, 1));
        m1 = fmaxf(m1, __shfl_xor_sync(0xffffffffu, m1, 2));
        float s0 = 0.f, s1 = 0.f;
        #pragma unroll
        for (int nt = 0; nt < 8; nt++) {
            acc[mt][nt][0] = __expf(acc[mt][nt][0] - m0); s0 += acc[mt][nt][0];
            acc[mt][nt][1] = __expf(acc[mt][nt][1] - m0); s0 += acc[mt][nt][1];
            acc[mt][nt][2] = __expf(acc[mt][nt][2] - m1); s1 += acc[mt][nt][2];
            acc[mt][nt][3] = __expf(acc[mt][nt][3] - m1); s1 += acc[mt][nt][3];
        }
        s0 += __shfl_xor_sync(0xffffffffu, s0, 1);
        s0 += __shfl_xor_sync(0xffffffffu, s0, 2);
        s1 += __shfl_xor_sync(0xffffffffu, s1, 1);
        s1 += __shfl_xor_sync(0xffffffffu, s1, 2);
        float i0 = 1.f / s0, i1 = 1.f / s1;
        #pragma unroll
        for (int nt = 0; nt < 8; nt++) {
            acc[mt][nt][0] *= i0; acc[mt][nt][1] *= i0;
            acc[mt][nt][2] *= i1; acc[mt][nt][3] *= i1;
        }
    }

    unsigned pf[4][4][4];
    #pragma unroll
    for (int mt = 0; mt < 4; mt++)
        #pragma unroll
        for (int kt = 0; kt < 4; kt++) {
            pf[mt][kt][0] = pack_h2(acc[mt][2 * kt][0],     acc[mt][2 * kt][1]);
            pf[mt][kt][1] = pack_h2(acc[mt][2 * kt][2],     acc[mt][2 * kt][3]);
            pf[mt][kt][2] = pack_h2(acc[mt][2 * kt + 1][0], acc[mt][2 * kt + 1][1]);
            pf[mt][kt][3] = pack_h2(acc[mt][2 * kt + 1][2], acc[mt][2 * kt + 1][3]);
        }

    float O[4][4][4];
    #pragma unroll
    for (int mt = 0; mt < 4; mt++)
        #pragma unroll
        for (int nt = 0; nt < 4; nt++)
            #pragma unroll
            for (int r = 0; r < 4; r++) O[mt][nt][r] = 0.f;
    #pragma unroll
    for (int kt = 0; kt < 4; kt++)
        #pragma unroll
        for (int np = 0; np < 2; np++) {
            int row = kt * 16 + ((quad & 1) << 3) + lr;
            int col = 512 + h * 32 + np * 16 + ((quad >> 1) << 3);
            unsigned bt[4];
            ldsm4t(bt, smem_u32(blob + row * BLOB_STRIDE + col));
            #pragma unroll
            for (int mt = 0; mt < 4; mt++) {
                mma_f16(O[mt][2 * np],     pf[mt][kt], bt);
                mma_f16(O[mt][2 * np + 1], pf[mt][kt], bt + 2);
            }
        }

    #pragma unroll
    for (int mt = 0; mt < 4; mt++) {
        int r0 = mt * 16 + (lane >> 2);
        #pragma unroll
        for (int nt = 0; nt < 4; nt++) {
            int c0 = nt * 8 + ((lane & 3) << 1);
            __half* op = out + (size_t)(win * 64 + r0) * 256 + h * 32 + c0;
            *(__half2*)op = __floats2half2_rn(O[mt][nt][0], O[mt][nt][1]);
            *(__half2*)(op + 8 * 256) = __floats2half2_rn(O[mt][nt][2], O[mt][nt][3]);
        }
    }
}

// ---------------------------------------------------------------------------
// LN1: x1h = half(x(fp32) + LN(y fp16))
// ---------------------------------------------------------------------------
__global__ __launch_bounds__(256)
void ln1_kernel(const float* __restrict__ resid, const __half* __restrict__ y,
                const float* __restrict__ sc, const float* __restrict__ bi,
                __half* __restrict__ outh) {
    int warp = (blockIdx.x * 256 + threadIdx.x) >> 5;
    int lane = threadIdx.x & 31;
    if (warp >= MROWS) return;
    uint4 uy = *(const uint4*)(y + (size_t)warp * 256 + lane * 8);
    float v[8];
    {
        __half2* hp = (__half2*)&uy;
        #pragma unroll
        for (int i = 0; i < 4; i++) {
            float2 f = __half22float2(hp[i]);
            v[2 * i] = f.x; v[2 * i + 1] = f.y;
        }
    }
    float s = 0.f;
    #pragma unroll
    for (int i = 0; i < 8; i++) s += v[i];
    #pragma unroll
    for (int o = 16; o > 0; o >>= 1) s += __shfl_xor_sync(0xffffffffu, s, o);
    float mean = s * (1.f / 256.f);
    float sq = 0.f;
    #pragma unroll
    for (int i = 0; i < 8; i++) { float d = v[i] - mean; sq += d * d; }
    #pragma unroll
    for (int o = 16; o > 0; o >>= 1) sq += __shfl_xor_sync(0xffffffffu, sq, o);
    float rstd = rsqrtf(sq * (1.f / 256.f) + 1e-6f);
    const float* rr = resid + (size_t)warp * 256;
    float ov[8];
    #pragma unroll
    for (int i = 0; i < 8; i++) {
        int c = lane * 8 + i;
        ov[i] = rr[c] + (v[i] - mean) * rstd * sc[c] + bi[c];
    }
    uint4 u;
    u.x = pack_h2(ov[0], ov[1]); u.y = pack_h2(ov[2], ov[3]);
    u.z = pack_h2(ov[4], ov[5]); u.w = pack_h2(ov[6], ov[7]);
    *(uint4*)(outh + (size_t)warp * 256 + lane * 8) = u;
}

// ---------------------------------------------------------------------------
// LN2: out(fp32) = x1h(fp16) + LN(h2 fp16)
// ---------------------------------------------------------------------------
__global__ __launch_bounds__(256)
void ln2_kernel(const __half* __restrict__ resid, const __half* __restrict__ y,
                const float* __restrict__ sc, const float* __restrict__ bi,
                float* __restrict__ out) {
    int warp = (blockIdx.x * 256 + threadIdx.x) >> 5;
    int lane = threadIdx.x & 31;
    if (warp >= MROWS) return;
    uint4 uy = *(const uint4*)(y + (size_t)warp * 256 + lane * 8);
    float v[8];
    {
        __half2* hp = (__half2*)&uy;
        #pragma unroll
        for (int i = 0; i < 4; i++) {
            float2 f = __half22float2(hp[i]);
            v[2 * i] = f.x; v[2 * i + 1] = f.y;
        }
    }
    float s = 0.f;
    #pragma unroll
    for (int i = 0; i < 8; i++) s += v[i];
    #pragma unroll
    for (int o = 16; o > 0; o >>= 1) s += __shfl_xor_sync(0xffffffffu, s, o);
    float mean = s * (1.f / 256.f);
    float sq = 0.f;
    #pragma unroll
    for (int i = 0; i < 8; i++) { float d = v[i] - mean; sq += d * d; }
    #pragma unroll
    for (int o = 16; o > 0; o >>= 1) sq += __shfl_xor_sync(0xffffffffu, sq, o);
    float rstd = rsqrtf(sq * (1.f / 256.f) + 1e-6f);
    uint4 ur = *(const uint4*)(resid + (size_t)warp * 256 + lane * 8);
    float rv[8];
    {
        __half2* hp = (__half2*)&ur;
        #pragma unroll
        for (int i = 0; i < 4; i++) {
            float2 f = __half22float2(hp[i]);
            rv[2 * i] = f.x; rv[2 * i + 1] = f.y;
        }
    }
    float* op = out + (size_t)warp * 256;
    #pragma unroll
    for (int i = 0; i < 8; i += 4) {
        int c = lane * 8 + i;
        float4 o4;
        o4.x = rv[i]     + (v[i]     - mean) * rstd * sc[c]     + bi[c];
        o4.y = rv[i + 1] + (v[i + 1] - mean) * rstd * sc[c + 1] + bi[c + 1];
        o4.z = rv[i + 2] + (v[i + 2] - mean) * rstd * sc[c + 2] + bi[c + 2];
        o4.w = rv[i + 3] + (v[i + 3] - mean) * rstd * sc[c + 3] + bi[c + 3];
        *(float4*)(op + c) = o4;
    }
}

// ---------------------------------------------------------------------------
extern "C" void kernel_launch(void* const* d_in, const int* in_sizes, int n_in,
                              void* d_out, int out_size) {
    const float* x       = (const float*)d_in[0];
    const float* qkv_w   = (const float*)d_in[1];
    const float* q_bias  = (const float*)d_in[2];
    const float* v_bias  = (const float*)d_in[3];
    const float* lscale  = (const float*)d_in[4];
    const float* cpb_w1  = (const float*)d_in[5];
    const float* cpb_b1  = (const float*)d_in[6];
    const float* cpb_w2  = (const float*)d_in[7];
    const float* proj_w  = (const float*)d_in[8];
    const float* proj_b  = (const float*)d_in[9];
    const float* n1s     = (const float*)d_in[10];
    const float* n1b     = (const float*)d_in[11];
    const float* n2s     = (const float*)d_in[12];
    const float* n2b     = (const float*)d_in[13];
    const float* fc1_w   = (const float*)d_in[14];
    const float* fc1_b   = (const float*)d_in[15];
    const float* fc2_w   = (const float*)d_in[16];
    const float* fc2_b   = (const float*)d_in[17];
    float* out = (float*)d_out;

    void *p_qkvh, *p_attn, *p_y, *p_x1h, *p_h, *p_h2, *p_xh, *p_qb, *p_rm;
    void *p_wqkv, *p_wproj, *p_wfc1, *p_wfc2;
    cudaGetSymbolAddress(&p_qkvh, g_qkvh);
    cudaGetSymbolAddress(&p_attn, g_attn);
    cudaGetSymbolAddress(&p_y,    g_y);
    cudaGetSymbolAddress(&p_x1h,  g_x1h);
    cudaGetSymbolAddress(&p_h,    g_h);
    cudaGetSymbolAddress(&p_h2,   g_h2);
    cudaGetSymbolAddress(&p_xh,   g_xh);
    cudaGetSymbolAddress(&p_qb,   g_qkvbias);
    cudaGetSymbolAddress(&p_rm,   g_rowmap);
    cudaGetSymbolAddress(&p_wqkv,  g_wqkv_h);
    cudaGetSymbolAddress(&p_wproj, g_wproj_h);
    cudaGetSymbolAddress(&p_wfc1,  g_wfc1_h);
    cudaGetSymbolAddress(&p_wfc2,  g_wfc2_h);

    cudaFuncSetAttribute(attn_kernel, cudaFuncAttributeMaxDynamicSharedMemorySize,
                         SMEM_ATTN);
    cudaFuncSetAttribute(gemm_f16<false, false, true>,
                         cudaFuncAttributeMaxDynamicSharedMemorySize, SMEM_GEMM);
    cudaFuncSetAttribute(gemm_f16<false, true, true>,
                         cudaFuncAttributeMaxDynamicSharedMemorySize, SMEM_GEMM);
    cudaFuncSetAttribute(gemm_f16<true, false, true>,
                         cudaFuncAttributeMaxDynamicSharedMemorySize, SMEM_GEMM);

    prep_kernel<<<1, 256>>>(lscale, cpb_w1, cpb_b1, cpb_w2, q_bias, v_bias);
    rowmap_kernel<<<512, 256>>>();
    xgather_kernel<<<16384, 256>>>(x);
    wtrans_kernel<<<768,  256>>>(qkv_w,  (__half*)p_wqkv,  256, 768);
    wtrans_kernel<<<256,  256>>>(proj_w, (__half*)p_wproj, 256, 256);
    wtrans_kernel<<<1024, 256>>>(fc1_w,  (__half*)p_wfc1,  256, 1024);
    wtrans_kernel<<<1024, 256>>>(fc2_w,  (__half*)p_wfc2,  1024, 256);

    // qkv = xh @ qkv_w + qkv_bias  -> fp16
    gemm_f16<false, false, true><<<dim3(6, 1024), 256, SMEM_GEMM>>>(
        (const __half*)p_xh, (const __half*)p_wqkv, (const float*)p_qb,
        p_qkvh, 768, 256, nullptr);

    attn_kernel<<<2048, 256, SMEM_ATTN>>>((const __half*)p_qkvh, (__half*)p_attn);

    // y = scatter(attn @ proj_w + proj_b)  -> fp16
    gemm_f16<false, true, true><<<dim3(2, 1024), 256, SMEM_GEMM>>>(
        (const __half*)p_attn, (const __half*)p_wproj, proj_b,
        p_y, 256, 256, (const int*)p_rm);

    // x1h = half(x + LN(y))
    ln1_kernel<<<MROWS / 8, 256>>>(x, (const __half*)p_y, n1s, n1b, (__half*)p_x1h);

    // h = gelu(x1h @ fc1_w + fc1_b)  -> fp16
    gemm_f16<true, false, true><<<dim3(8, 1024), 256, SMEM_GEMM>>>(
        (const __half*)p_x1h, (const __half*)p_wfc1, fc1_b,
        p_h, 1024, 256, nullptr);

    // h2 = h @ fc2_w + fc2_b  -> fp16
    gemm_f16<false, false, true><<<dim3(2, 1024), 256, SMEM_GEMM>>>(
        (const __half*)p_h, (const __half*)p_wfc2, fc2_b,
        p_h2, 256, 1024, nullptr);

    // out = x1h + LN(h2)
    ln2_kernel<<<MROWS / 8, 256>>>((const __half*)p_x1h, (const __half*)p_h2,
                                   n2s, n2b, out);
}